// round 10
// baseline (speedup 1.0000x reference)
#include <cuda_runtime.h>
#include <cstdint>
#include <cstddef>

#define F 128
#define MAXN 500000
#define CAP 64       // bucket capacity per row (Poisson(1): overflow prob ~0)

// -------- scratch (device globals; no allocation allowed) --------
__device__ float d_bufA[(size_t)MAXN * F];        // 256 MB
__device__ float d_bufB[(size_t)MAXN * F];        // 256 MB
__device__ int   d_csr[(size_t)MAXN * CAP];       // 128 MB padded buckets
__device__ int   d_cnt[MAXN];                     // row degrees
__device__ float d_s[MAXN];
__device__ float d_gsum[F];
__device__ __align__(16) float d_el[4];

// -------- tf32 helpers --------
static __device__ __forceinline__ uint32_t f2tf32(float f) {
    uint32_t r;
    asm("cvt.rna.tf32.f32 %0, %1;" : "=r"(r) : "f"(f));
    return r;
}
// D(16x8,f32) += A(16x8,tf32 row) * B(8x8,tf32 col)
static __device__ __forceinline__ void mma_tf32(float* c, const uint4& a, const uint2& b) {
    asm("mma.sync.aligned.m16n8k8.row.col.f32.tf32.tf32.f32 "
        "{%0,%1,%2,%3}, {%4,%5,%6,%7}, {%8,%9}, {%0,%1,%2,%3};"
        : "+f"(c[0]), "+f"(c[1]), "+f"(c[2]), "+f"(c[3])
        : "r"(a.x), "r"(a.y), "r"(a.z), "r"(a.w), "r"(b.x), "r"(b.y));
}

// -------- zero counters --------
__global__ void zero_kernel() {
    int i = blockIdx.x * blockDim.x + threadIdx.x;
    if (i < MAXN) d_cnt[i] = 0;
    if (i < F) d_gsum[i] = 0.f;
}

// -------- bucket fill: csr[row][p++] = col --------
__global__ void fill_kernel(const int* __restrict__ ei, int E) {
    int e = blockIdx.x * blockDim.x + threadIdx.x;
    if (e < E) {
        int r = ei[e];
        int p = atomicAdd(&d_cnt[r], 1);
        if (p < CAP) d_csr[((size_t)r << 6) + p] = ei[E + e];
    }
}

// -------- per-position norm: s[i] = dis[row[i]] * dis[col[i]] --------
__global__ void s_kernel(const int* __restrict__ ei, int n, int E) {
    int i = blockIdx.x * blockDim.x + threadIdx.x;
    if (i < n) {
        float dr = (float)d_cnt[ei[i]];
        float dc = (float)d_cnt[ei[E + i]];
        float a = dr > 0.f ? rsqrtf(dr) : 0.f;
        float b = dc > 0.f ? rsqrtf(dc) : 0.f;
        d_s[i] = a * b;
    }
}

// -------- fused tensor-core GEMM: out[i] = (relu?(X[i]) @ W + b) * s[i] --------
// Block 128x128, K=128, 512 threads (16 warps, 4x4 warp grid, warp tile 32x32).
// mma.sync m16n8k8 tf32. W split into Wh+Wl tf32 terms (fp32-grade weights);
// X single rna-tf32 (zero-mean rounding, washed out by the 500k mean-pool).
// SMEM holds operands PRE-PERMUTED into fragment layout, XOR-swizzled by
// (ks&7) on the lane index: mainloop A = 1 LDS.128, B = 1 LDS.64 per frag.
// Fragment maps (PTX m16n8k8.tf32): g=lane>>2, tig=lane&3;
//   A: a0=A[g][tig] a1=A[g+8][tig] a2=A[g][tig+4] a3=A[g+8][tig+4]
//   B: b0=B[tig][col_g] b1=B[tig+4][col_g]
//   D: c0=D[g][2tig] c1=D[g][2tig+1] c2=D[g+8][2tig] c3=D[g+8][2tig+1]
#define AF_OFF 0          // 8 mc x 16 ks x 32 lanes x 4 u32 = 16384
#define BH_OFF 16384      // 16 nc x 16 ks x 32 lanes x 2 u32 = 16384
#define BL_OFF 32768
#define GSM_BYTES (49152 * 4)

__global__ __launch_bounds__(512)
void gemm_kernel(const float* __restrict__ X, const float* __restrict__ W,
                 const float* __restrict__ bias,
                 float* __restrict__ out, int n, int relu_in) {
    extern __shared__ float smf[];
    uint32_t* smu = (uint32_t*)smf;
    const int tid = threadIdx.x;
    const int w = tid >> 5, l = tid & 31;
    const int wm = w >> 2, wn = w & 3;
    const int g = l >> 2, tig = l & 3;
    const int rbase = blockIdx.x * 128;

    // ---- stage A fragments: 4096 float4, 8 per thread
    #pragma unroll
    for (int it = 0; it < 8; it++) {
        int lin = it * 512 + tid;
        int r = lin >> 5, q = lin & 31;
        int row = rbase + r;
        float4 v = make_float4(0.f, 0.f, 0.f, 0.f);
        if (row < n) v = ((const float4*)(X + (size_t)row * F))[q];
        if (relu_in) {
            v.x = fmaxf(v.x, 0.f); v.y = fmaxf(v.y, 0.f);
            v.z = fmaxf(v.z, 0.f); v.w = fmaxf(v.w, 0.f);
        }
        int mc = r >> 4, gp = r & 15, gg = gp & 7;
        int ks = q >> 1;
        int slot = ((q & 1) << 1) + (gp >> 3);     // {a0,a1,a2,a3} position
        int base16 = (mc * 16 + ks) * 32;
        int sw = ks & 7;
        float vv[4] = { v.x, v.y, v.z, v.w };
        #pragma unroll
        for (int j = 0; j < 4; j++) {
            int lp = (gg * 4 + j) ^ sw;            // j = tig of element k0+j
            smu[AF_OFF + (base16 + lp) * 4 + slot] = f2tf32(vv[j]);
        }
    }
    // ---- stage B fragments (both splits): 4096 float4, 8 per thread
    #pragma unroll
    for (int it = 0; it < 8; it++) {
        int lin = it * 512 + tid;
        int k = lin >> 5, q = lin & 31;
        float4 wv4 = *(const float4*)(W + k * F + q * 4);
        int ks = k >> 3, kk = k & 7;
        int btig = kk & 3, sb = kk >> 2;           // b0 (k<4) / b1 (k>=4)
        int sw = ks & 7;
        float wv[4] = { wv4.x, wv4.y, wv4.z, wv4.w };
        #pragma unroll
        for (int j = 0; j < 4; j++) {
            int c = q * 4 + j;
            int nc = c >> 3, cg = c & 7;
            int lp = (cg * 4 + btig) ^ sw;
            int idx = ((nc * 16 + ks) * 32 + lp) * 2 + sb;
            uint32_t wh = f2tf32(wv[j]);
            float rem = wv[j] - __uint_as_float(wh);
            smu[BH_OFF + idx] = wh;
            smu[BL_OFF + idx] = f2tf32(rem);
        }
    }
    __syncthreads();

    // ---- mainloop: warp tile 32x32 = 2 m-tiles x 4 n-tiles
    float acc[2][4][4];
    #pragma unroll
    for (int mt = 0; mt < 2; mt++)
        #pragma unroll
        for (int nt = 0; nt < 4; nt++)
            #pragma unroll
            for (int j = 0; j < 4; j++) acc[mt][nt][j] = 0.f;

    #pragma unroll
    for (int ks = 0; ks < 16; ks++) {
        int lp = l ^ (ks & 7);
        uint4 af[2];
        #pragma unroll
        for (int mt = 0; mt < 2; mt++)
            af[mt] = *(const uint4*)&smu[AF_OFF + (((wm * 2 + mt) * 16 + ks) * 32 + lp) * 4];
        uint2 bh[4], bl[4];
        #pragma unroll
        for (int nt = 0; nt < 4; nt++) {
            int bidx = (((wn * 4 + nt) * 16 + ks) * 32 + lp) * 2;
            bh[nt] = *(const uint2*)&smu[BH_OFF + bidx];
            bl[nt] = *(const uint2*)&smu[BL_OFF + bidx];
        }
        #pragma unroll
        for (int mt = 0; mt < 2; mt++)
            #pragma unroll
            for (int nt = 0; nt < 4; nt++) {
                mma_tf32(acc[mt][nt], af[mt], bh[nt]);
                mma_tf32(acc[mt][nt], af[mt], bl[nt]);
            }
    }

    // ---- epilogue: bias + degree-norm scale, write fp32
    #pragma unroll
    for (int mt = 0; mt < 2; mt++) {
        int row_lo = rbase + wm * 32 + mt * 16 + g;
        int row_hi = row_lo + 8;
        float s_lo = (row_lo < n) ? d_s[row_lo] : 0.f;
        float s_hi = (row_hi < n) ? d_s[row_hi] : 0.f;
        #pragma unroll
        for (int nt = 0; nt < 4; nt++) {
            int col = wn * 32 + nt * 8 + tig * 2;
            float b0 = bias[col], b1 = bias[col + 1];
            if (row_lo < n) {
                float2 o = make_float2((acc[mt][nt][0] + b0) * s_lo,
                                       (acc[mt][nt][1] + b1) * s_lo);
                *(float2*)(out + (size_t)row_lo * F + col) = o;
            }
            if (row_hi < n) {
                float2 o = make_float2((acc[mt][nt][2] + b0) * s_hi,
                                       (acc[mt][nt][3] + b1) * s_hi);
                *(float2*)(out + (size_t)row_hi * F + col) = o;
            }
        }
    }
}

// -------- gather: dst[r] = sum over bucket(r) of src[col]  (warp per row) --------
__global__ void gather_kernel(const float* __restrict__ src,
                              float* __restrict__ dst, int n) {
    int warp = (blockIdx.x * blockDim.x + threadIdx.x) >> 5;
    int lane = threadIdx.x & 31;
    int nw = (gridDim.x * blockDim.x) >> 5;
    for (int r = warp; r < n; r += nw) {
        int cnt = d_cnt[r]; if (cnt > CAP) cnt = CAP;
        float4 acc = make_float4(0.f, 0.f, 0.f, 0.f);
        size_t base = (size_t)r << 6;
        for (int i = 0; i < cnt; i++) {
            int c = d_csr[base + i];
            float4 v = ((const float4*)(src + (size_t)c * F))[lane];
            acc.x += v.x; acc.y += v.y; acc.z += v.z; acc.w += v.w;
        }
        ((float4*)(dst + (size_t)r * F))[lane] = acc;
    }
}

// -------- gather + relu + column-sum fusion (never materializes agg2) --------
__global__ void gather_mean_kernel(const float* __restrict__ src, int n) {
    __shared__ float smr[128];
    int t = threadIdx.x;
    if (t < 128) smr[t] = 0.f;
    __syncthreads();
    int warp = (blockIdx.x * blockDim.x + t) >> 5;
    int lane = t & 31;
    int nw = (gridDim.x * blockDim.x) >> 5;
    float4 ps = make_float4(0.f, 0.f, 0.f, 0.f);
    for (int r = warp; r < n; r += nw) {
        int cnt = d_cnt[r]; if (cnt > CAP) cnt = CAP;
        float4 acc = make_float4(0.f, 0.f, 0.f, 0.f);
        size_t base = (size_t)r << 6;
        for (int i = 0; i < cnt; i++) {
            int c = d_csr[base + i];
            float4 v = ((const float4*)(src + (size_t)c * F))[lane];
            acc.x += v.x; acc.y += v.y; acc.z += v.z; acc.w += v.w;
        }
        ps.x += fmaxf(acc.x, 0.f); ps.y += fmaxf(acc.y, 0.f);
        ps.z += fmaxf(acc.z, 0.f); ps.w += fmaxf(acc.w, 0.f);
    }
    atomicAdd(&smr[lane * 4 + 0], ps.x);
    atomicAdd(&smr[lane * 4 + 1], ps.y);
    atomicAdd(&smr[lane * 4 + 2], ps.z);
    atomicAdd(&smr[lane * 4 + 3], ps.w);
    __syncthreads();
    if (t < 128) atomicAdd(&d_gsum[t], smr[t]);
}

// -------- latent head (1 block, 128 threads) --------
__global__ void head_kernel(const float* __restrict__ eps,
                            const float* __restrict__ Wmu, const float* __restrict__ bmu,
                            const float* __restrict__ Wlv, const float* __restrict__ blv,
                            const float* __restrict__ Wn,  const float* __restrict__ bn,
                            const float* __restrict__ We1, const float* __restrict__ be1,
                            const float* __restrict__ We2, const float* __restrict__ be2,
                            float* __restrict__ out, int n, int E) {
    __shared__ float zs[32];
    __shared__ float ehs[128];
    int t = threadIdx.x;
    float invN = 1.0f / (float)n;
    size_t ofs = 16 + (size_t)E * 4;
    if (t < 32) {
        float mu = bmu[t], lv = blv[t];
        for (int c = 0; c < 128; c++) {
            float g = d_gsum[c] * invN;
            mu += g * Wmu[c * 32 + t];
            lv += g * Wlv[c * 32 + t];
        }
        zs[t] = mu + eps[t] * expf(0.5f * lv);
        out[ofs + t] = mu;
        out[ofs + 32 + t] = lv;
    }
    __syncthreads();
    if (t < 16) {
        float v = bn[t];
        for (int j = 0; j < 32; j++) v += zs[j] * Wn[j * 16 + t];
        out[t] = v;
    }
    {
        float v = be1[t];
        for (int k = 0; k < 64; k++) v += zs[k & 31] * We1[k * 128 + t];
        ehs[t] = fmaxf(v, 0.f);
    }
    __syncthreads();
    if (t < 4) {
        float v = be2[t];
        for (int h2 = 0; h2 < 128; h2++) v += ehs[h2] * We2[h2 * 4 + t];
        d_el[t] = v;
    }
}

// -------- broadcast identical edge logits --------
__global__ void bcast_kernel(float* __restrict__ out, int E) {
    int e = blockIdx.x * blockDim.x + threadIdx.x;
    float4 v = *(const float4*)d_el;
    if (e < E) ((float4*)(out + 16))[e] = v;
}

extern "C" void kernel_launch(void* const* d_in, const int* in_sizes, int n_in,
                              void* d_out, int out_size) {
    const float* x   = (const float*)d_in[0];
    const int*   ei  = (const int*)d_in[1];      // int32 (JAX x64 disabled)
    const float* eps = (const float*)d_in[2];
    const float* W1  = (const float*)d_in[3];
    const float* b1  = (const float*)d_in[4];
    const float* W2  = (const float*)d_in[5];
    const float* b2  = (const float*)d_in[6];
    const float* Wmu = (const float*)d_in[7];
    const float* bmu = (const float*)d_in[8];
    const float* Wlv = (const float*)d_in[9];
    const float* blv = (const float*)d_in[10];
    const float* Wn  = (const float*)d_in[11];
    const float* bn  = (const float*)d_in[12];
    const float* We1 = (const float*)d_in[13];
    const float* be1 = (const float*)d_in[14];
    const float* We2 = (const float*)d_in[15];
    const float* be2 = (const float*)d_in[16];
    float* out = (float*)d_out;

    int n = in_sizes[0] / F;       // 500000
    int E = in_sizes[1] / 2;       // 500000

    float* bufA_p = nullptr;
    float* bufB_p = nullptr;
    cudaGetSymbolAddress((void**)&bufA_p, d_bufA);
    cudaGetSymbolAddress((void**)&bufB_p, d_bufB);

    cudaFuncSetAttribute(gemm_kernel,
                         cudaFuncAttributeMaxDynamicSharedMemorySize, GSM_BYTES);

    int gblocks = (n + 127) / 128;

    zero_kernel<<<(MAXN + 255) / 256, 256>>>();
    fill_kernel<<<(E + 255) / 256, 256>>>(ei, E);
    s_kernel<<<(n + 255) / 256, 256>>>(ei, n, E);

    // conv1: bufA = (x@W1+b1)*s ; bufB = gather(bufA)
    gemm_kernel<<<gblocks, 512, GSM_BYTES>>>(x, W1, b1, bufA_p, n, 0);
    gather_kernel<<<2048, 256>>>(bufA_p, bufB_p, n);

    // conv2: bufA = (relu(bufB)@W2+b2)*s ; fused gather+relu+colsum
    gemm_kernel<<<gblocks, 512, GSM_BYTES>>>(bufB_p, W2, b2, bufA_p, n, 1);
    gather_mean_kernel<<<2048, 256>>>(bufA_p, n);

    // latent head ; edge-logit broadcast
    head_kernel<<<1, 128>>>(eps, Wmu, bmu, Wlv, blv, Wn, bn, We1, be1, We2, be2,
                            out, n, E);
    bcast_kernel<<<(E + 255) / 256, 256>>>(out, E);
}

// round 11
// speedup vs baseline: 2.1325x; 2.1325x over previous
#include <cuda_runtime.h>
#include <cstdint>
#include <cstddef>

#define F 128
#define MAXN 500000
#define CAP 64       // bucket capacity per row (Poisson(1): overflow prob ~0)

// -------- scratch (device globals; no allocation allowed) --------
__device__ float d_bufA[(size_t)MAXN * F];        // 256 MB
__device__ float d_bufB[(size_t)MAXN * F];        // 256 MB
__device__ int   d_csr[(size_t)MAXN * CAP];       // 128 MB padded buckets
__device__ int   d_cnt[MAXN];                     // row degrees
__device__ float d_s[MAXN];
__device__ float d_gsum[F];
__device__ __align__(16) float d_el[4];
__device__ __align__(16) uint32_t d_wf1[32768];   // W1 fragments: [H 16384 | L 16384]
__device__ __align__(16) uint32_t d_wf2[32768];   // W2 fragments

// -------- tf32 helpers --------
static __device__ __forceinline__ uint32_t f2tf32(float f) {
    uint32_t r;
    asm("cvt.rna.tf32.f32 %0, %1;" : "=r"(r) : "f"(f));
    return r;
}
// D(16x8,f32) += A(16x8,tf32 row) * B(8x8,tf32 col)
static __device__ __forceinline__ void mma_tf32(float* c, const uint4& a, const uint2& b) {
    asm("mma.sync.aligned.m16n8k8.row.col.f32.tf32.tf32.f32 "
        "{%0,%1,%2,%3}, {%4,%5,%6,%7}, {%8,%9}, {%0,%1,%2,%3};"
        : "+f"(c[0]), "+f"(c[1]), "+f"(c[2]), "+f"(c[3])
        : "r"(a.x), "r"(a.y), "r"(a.z), "r"(a.w), "r"(b.x), "r"(b.y));
}

// -------- zero counters --------
__global__ void zero_kernel() {
    int i = blockIdx.x * blockDim.x + threadIdx.x;
    if (i < MAXN) d_cnt[i] = 0;
    if (i < F) d_gsum[i] = 0.f;
}

// -------- bucket fill: csr[row][p++] = col --------
__global__ void fill_kernel(const int* __restrict__ ei, int E) {
    int e = blockIdx.x * blockDim.x + threadIdx.x;
    if (e < E) {
        int r = ei[e];
        int p = atomicAdd(&d_cnt[r], 1);
        if (p < CAP) d_csr[((size_t)r << 6) + p] = ei[E + e];
    }
}

// -------- per-position norm: s[i] = dis[row[i]] * dis[col[i]] --------
__global__ void s_kernel(const int* __restrict__ ei, int n, int E) {
    int i = blockIdx.x * blockDim.x + threadIdx.x;
    if (i < n) {
        float dr = (float)d_cnt[ei[i]];
        float dc = (float)d_cnt[ei[E + i]];
        float a = dr > 0.f ? rsqrtf(dr) : 0.f;
        float b = dc > 0.f ? rsqrtf(dc) : 0.f;
        d_s[i] = a * b;
    }
}

// -------- one-time W -> fragment-layout transform (grid 8 x 512) --------
// Layout identical to the gemm smem expectation:
//   idx = ((nc*16+ks)*32+lp)*2 + sb;  H at dst[idx], L at dst[16384+idx]
__global__ void wprep_kernel(const float* __restrict__ W, uint32_t* __restrict__ dst) {
    int lin = blockIdx.x * 512 + threadIdx.x;   // 0..4095
    int k = lin >> 5, q = lin & 31;
    float4 wv4 = *(const float4*)(W + k * F + q * 4);
    int ks = k >> 3, kk = k & 7;
    int btig = kk & 3, sb = kk >> 2;
    int sw = ks & 7;
    float wv[4] = { wv4.x, wv4.y, wv4.z, wv4.w };
    #pragma unroll
    for (int j = 0; j < 4; j++) {
        int c = q * 4 + j;
        int nc = c >> 3, cg = c & 7;
        int lp = (cg * 4 + btig) ^ sw;
        int idx = ((nc * 16 + ks) * 32 + lp) * 2 + sb;
        uint32_t wh = f2tf32(wv[j]);
        float rem = wv[j] - __uint_as_float(wh);
        dst[idx] = wh;
        dst[16384 + idx] = f2tf32(rem);
    }
}

// -------- fused tensor-core GEMM: out[i] = (relu?(X[i]) @ W + b) * s[i] --------
// Block 128x128, K=128, 512 threads (16 warps, 4x4 warp grid, warp tile 32x32).
// mma.sync m16n8k8 tf32, W = Wh+Wl split (fp32-grade weights), X rna-tf32.
// B fragments are PRECOMPUTED in global (wprep) and copied linearly into
// smem (coalesced, conflict-free) — no per-block transform.
// Fragment maps (PTX m16n8k8.tf32): g=lane>>2, tig=lane&3;
//   A: a0=A[g][tig] a1=A[g+8][tig] a2=A[g][tig+4] a3=A[g+8][tig+4]
//   B: b0=B[tig][col_g] b1=B[tig+4][col_g]
//   D: c0=D[g][2tig] c1=D[g][2tig+1] c2=D[g+8][2tig] c3=D[g+8][2tig+1]
#define AF_OFF 0          // 8 mc x 16 ks x 32 lanes x 4 u32 = 16384
#define BH_OFF 16384      // 16 nc x 16 ks x 32 lanes x 2 u32 = 16384
#define BL_OFF 32768
#define GSM_BYTES (49152 * 4)

__global__ __launch_bounds__(512)
void gemm_kernel(const float* __restrict__ X, const uint32_t* __restrict__ wf,
                 const float* __restrict__ bias,
                 float* __restrict__ out, int n, int relu_in) {
    extern __shared__ float smf[];
    uint32_t* smu = (uint32_t*)smf;
    const int tid = threadIdx.x;
    const int w = tid >> 5, l = tid & 31;
    const int wm = w >> 2, wn = w & 3;
    const int g = l >> 2, tig = l & 3;
    const int rbase = blockIdx.x * 128;

    // ---- stage A fragments: 4096 float4, 8 per thread
    #pragma unroll
    for (int it = 0; it < 8; it++) {
        int lin = it * 512 + tid;
        int r = lin >> 5, q = lin & 31;
        int row = rbase + r;
        float4 v = make_float4(0.f, 0.f, 0.f, 0.f);
        if (row < n) v = ((const float4*)(X + (size_t)row * F))[q];
        if (relu_in) {
            v.x = fmaxf(v.x, 0.f); v.y = fmaxf(v.y, 0.f);
            v.z = fmaxf(v.z, 0.f); v.w = fmaxf(v.w, 0.f);
        }
        int mc = r >> 4, gp = r & 15, gg = gp & 7;
        int ks = q >> 1;
        int slot = ((q & 1) << 1) + (gp >> 3);     // {a0,a1,a2,a3} position
        int base16 = (mc * 16 + ks) * 32;
        int sw = ks & 7;
        float vv[4] = { v.x, v.y, v.z, v.w };
        #pragma unroll
        for (int j = 0; j < 4; j++) {
            int lp = (gg * 4 + j) ^ sw;            // j = tig of element k0+j
            smu[AF_OFF + (base16 + lp) * 4 + slot] = f2tf32(vv[j]);
        }
    }
    // ---- stage B fragments: linear coalesced copy from precomputed global
    {
        const uint4* src = (const uint4*)wf;
        uint4* dstB = (uint4*)(smu + BH_OFF);      // covers BH then BL (contiguous)
        #pragma unroll
        for (int it = 0; it < 16; it++)
            dstB[it * 512 + tid] = src[it * 512 + tid];
    }
    __syncthreads();

    // ---- mainloop: warp tile 32x32 = 2 m-tiles x 4 n-tiles
    float acc[2][4][4];
    #pragma unroll
    for (int mt = 0; mt < 2; mt++)
        #pragma unroll
        for (int nt = 0; nt < 4; nt++)
            #pragma unroll
            for (int j = 0; j < 4; j++) acc[mt][nt][j] = 0.f;

    #pragma unroll
    for (int ks = 0; ks < 16; ks++) {
        int lp = l ^ (ks & 7);
        uint4 af[2];
        #pragma unroll
        for (int mt = 0; mt < 2; mt++)
            af[mt] = *(const uint4*)&smu[AF_OFF + (((wm * 2 + mt) * 16 + ks) * 32 + lp) * 4];
        uint2 bh[4], bl[4];
        #pragma unroll
        for (int nt = 0; nt < 4; nt++) {
            int bidx = (((wn * 4 + nt) * 16 + ks) * 32 + lp) * 2;
            bh[nt] = *(const uint2*)&smu[BH_OFF + bidx];
            bl[nt] = *(const uint2*)&smu[BL_OFF + bidx];
        }
        #pragma unroll
        for (int mt = 0; mt < 2; mt++)
            #pragma unroll
            for (int nt = 0; nt < 4; nt++) {
                mma_tf32(acc[mt][nt], af[mt], bh[nt]);
                mma_tf32(acc[mt][nt], af[mt], bl[nt]);
            }
    }

    // ---- epilogue: bias + degree-norm scale, write fp32
    #pragma unroll
    for (int mt = 0; mt < 2; mt++) {
        int row_lo = rbase + wm * 32 + mt * 16 + g;
        int row_hi = row_lo + 8;
        float s_lo = (row_lo < n) ? d_s[row_lo] : 0.f;
        float s_hi = (row_hi < n) ? d_s[row_hi] : 0.f;
        #pragma unroll
        for (int nt = 0; nt < 4; nt++) {
            int col = wn * 32 + nt * 8 + tig * 2;
            float b0 = bias[col], b1 = bias[col + 1];
            if (row_lo < n) {
                float2 o = make_float2((acc[mt][nt][0] + b0) * s_lo,
                                       (acc[mt][nt][1] + b1) * s_lo);
                *(float2*)(out + (size_t)row_lo * F + col) = o;
            }
            if (row_hi < n) {
                float2 o = make_float2((acc[mt][nt][2] + b0) * s_hi,
                                       (acc[mt][nt][3] + b1) * s_hi);
                *(float2*)(out + (size_t)row_hi * F + col) = o;
            }
        }
    }
}

// -------- gather: dst[r] = sum over bucket(r) of src[col]  (warp per row) --------
__global__ void gather_kernel(const float* __restrict__ src,
                              float* __restrict__ dst, int n) {
    int warp = (blockIdx.x * blockDim.x + threadIdx.x) >> 5;
    int lane = threadIdx.x & 31;
    int nw = (gridDim.x * blockDim.x) >> 5;
    for (int r = warp; r < n; r += nw) {
        int cnt = d_cnt[r]; if (cnt > CAP) cnt = CAP;
        float4 acc = make_float4(0.f, 0.f, 0.f, 0.f);
        size_t base = (size_t)r << 6;
        for (int i = 0; i < cnt; i++) {
            int c = d_csr[base + i];
            float4 v = ((const float4*)(src + (size_t)c * F))[lane];
            acc.x += v.x; acc.y += v.y; acc.z += v.z; acc.w += v.w;
        }
        ((float4*)(dst + (size_t)r * F))[lane] = acc;
    }
}

// -------- gather + relu + column-sum fusion (never materializes agg2) --------
__global__ void gather_mean_kernel(const float* __restrict__ src, int n) {
    __shared__ float smr[128];
    int t = threadIdx.x;
    if (t < 128) smr[t] = 0.f;
    __syncthreads();
    int warp = (blockIdx.x * blockDim.x + t) >> 5;
    int lane = t & 31;
    int nw = (gridDim.x * blockDim.x) >> 5;
    float4 ps = make_float4(0.f, 0.f, 0.f, 0.f);
    for (int r = warp; r < n; r += nw) {
        int cnt = d_cnt[r]; if (cnt > CAP) cnt = CAP;
        float4 acc = make_float4(0.f, 0.f, 0.f, 0.f);
        size_t base = (size_t)r << 6;
        for (int i = 0; i < cnt; i++) {
            int c = d_csr[base + i];
            float4 v = ((const float4*)(src + (size_t)c * F))[lane];
            acc.x += v.x; acc.y += v.y; acc.z += v.z; acc.w += v.w;
        }
        ps.x += fmaxf(acc.x, 0.f); ps.y += fmaxf(acc.y, 0.f);
        ps.z += fmaxf(acc.z, 0.f); ps.w += fmaxf(acc.w, 0.f);
    }
    atomicAdd(&smr[lane * 4 + 0], ps.x);
    atomicAdd(&smr[lane * 4 + 1], ps.y);
    atomicAdd(&smr[lane * 4 + 2], ps.z);
    atomicAdd(&smr[lane * 4 + 3], ps.w);
    __syncthreads();
    if (t < 128) atomicAdd(&d_gsum[t], smr[t]);
}

// -------- latent head (1 block, 128 threads) --------
__global__ void head_kernel(const float* __restrict__ eps,
                            const float* __restrict__ Wmu, const float* __restrict__ bmu,
                            const float* __restrict__ Wlv, const float* __restrict__ blv,
                            const float* __restrict__ Wn,  const float* __restrict__ bn,
                            const float* __restrict__ We1, const float* __restrict__ be1,
                            const float* __restrict__ We2, const float* __restrict__ be2,
                            float* __restrict__ out, int n, int E) {
    __shared__ float zs[32];
    __shared__ float ehs[128];
    int t = threadIdx.x;
    float invN = 1.0f / (float)n;
    size_t ofs = 16 + (size_t)E * 4;
    if (t < 32) {
        float mu = bmu[t], lv = blv[t];
        for (int c = 0; c < 128; c++) {
            float g = d_gsum[c] * invN;
            mu += g * Wmu[c * 32 + t];
            lv += g * Wlv[c * 32 + t];
        }
        zs[t] = mu + eps[t] * expf(0.5f * lv);
        out[ofs + t] = mu;
        out[ofs + 32 + t] = lv;
    }
    __syncthreads();
    if (t < 16) {
        float v = bn[t];
        for (int j = 0; j < 32; j++) v += zs[j] * Wn[j * 16 + t];
        out[t] = v;
    }
    {
        float v = be1[t];
        for (int k = 0; k < 64; k++) v += zs[k & 31] * We1[k * 128 + t];
        ehs[t] = fmaxf(v, 0.f);
    }
    __syncthreads();
    if (t < 4) {
        float v = be2[t];
        for (int h2 = 0; h2 < 128; h2++) v += ehs[h2] * We2[h2 * 4 + t];
        d_el[t] = v;
    }
}

// -------- broadcast identical edge logits --------
__global__ void bcast_kernel(float* __restrict__ out, int E) {
    int e = blockIdx.x * blockDim.x + threadIdx.x;
    float4 v = *(const float4*)d_el;
    if (e < E) ((float4*)(out + 16))[e] = v;
}

extern "C" void kernel_launch(void* const* d_in, const int* in_sizes, int n_in,
                              void* d_out, int out_size) {
    const float* x   = (const float*)d_in[0];
    const int*   ei  = (const int*)d_in[1];      // int32 (JAX x64 disabled)
    const float* eps = (const float*)d_in[2];
    const float* W1  = (const float*)d_in[3];
    const float* b1  = (const float*)d_in[4];
    const float* W2  = (const float*)d_in[5];
    const float* b2  = (const float*)d_in[6];
    const float* Wmu = (const float*)d_in[7];
    const float* bmu = (const float*)d_in[8];
    const float* Wlv = (const float*)d_in[9];
    const float* blv = (const float*)d_in[10];
    const float* Wn  = (const float*)d_in[11];
    const float* bn  = (const float*)d_in[12];
    const float* We1 = (const float*)d_in[13];
    const float* be1 = (const float*)d_in[14];
    const float* We2 = (const float*)d_in[15];
    const float* be2 = (const float*)d_in[16];
    float* out = (float*)d_out;

    int n = in_sizes[0] / F;       // 500000
    int E = in_sizes[1] / 2;       // 500000

    float* bufA_p = nullptr;
    float* bufB_p = nullptr;
    uint32_t* wf1_p = nullptr;
    uint32_t* wf2_p = nullptr;
    cudaGetSymbolAddress((void**)&bufA_p, d_bufA);
    cudaGetSymbolAddress((void**)&bufB_p, d_bufB);
    cudaGetSymbolAddress((void**)&wf1_p, d_wf1);
    cudaGetSymbolAddress((void**)&wf2_p, d_wf2);

    cudaFuncSetAttribute(gemm_kernel,
                         cudaFuncAttributeMaxDynamicSharedMemorySize, GSM_BYTES);

    int gblocks = (n + 127) / 128;

    zero_kernel<<<(MAXN + 255) / 256, 256>>>();
    fill_kernel<<<(E + 255) / 256, 256>>>(ei, E);
    s_kernel<<<(n + 255) / 256, 256>>>(ei, n, E);
    wprep_kernel<<<8, 512>>>(W1, wf1_p);
    wprep_kernel<<<8, 512>>>(W2, wf2_p);

    // conv1: bufA = (x@W1+b1)*s ; bufB = gather(bufA)
    gemm_kernel<<<gblocks, 512, GSM_BYTES>>>(x, wf1_p, b1, bufA_p, n, 0);
    gather_kernel<<<2048, 256>>>(bufA_p, bufB_p, n);

    // conv2: bufA = (relu(bufB)@W2+b2)*s ; fused gather+relu+colsum
    gemm_kernel<<<gblocks, 512, GSM_BYTES>>>(bufB_p, wf2_p, b2, bufA_p, n, 1);
    gather_mean_kernel<<<2048, 256>>>(bufA_p, n);

    // latent head ; edge-logit broadcast
    head_kernel<<<1, 128>>>(eps, Wmu, bmu, Wlv, blv, Wn, bn, We1, be1, We2, be2,
                            out, n, E);
    bcast_kernel<<<(E + 255) / 256, 256>>>(out, E);
}

// round 12
// speedup vs baseline: 2.6936x; 1.2631x over previous
#include <cuda_runtime.h>
#include <cstdint>
#include <cstddef>

#define F 128
#define MAXN 500000
#define CAP 64       // bucket capacity per row (Poisson(1): overflow prob ~0)

// -------- scratch (device globals; no allocation allowed) --------
__device__ float d_bufA[(size_t)MAXN * F];        // 256 MB
__device__ float d_bufB[(size_t)MAXN * F];        // 256 MB
__device__ int   d_csr[(size_t)MAXN * CAP];       // 128 MB padded buckets
__device__ int   d_cnt[MAXN];                     // row degrees
__device__ float d_s[MAXN];
__device__ float d_gsum[F];
__device__ __align__(16) float d_el[4];
__device__ __align__(16) uint32_t d_wf1[32768];   // W1 fragments: [H 16384 | L 16384]
__device__ __align__(16) uint32_t d_wf2[32768];   // W2 fragments

// -------- tf32 helpers --------
static __device__ __forceinline__ uint32_t f2tf32(float f) {
    uint32_t r;
    asm("cvt.rna.tf32.f32 %0, %1;" : "=r"(r) : "f"(f));
    return r;
}
// D(16x8,f32) += A(16x8,tf32 row) * B(8x8,tf32 col)
static __device__ __forceinline__ void mma_tf32(float* c, const uint4& a, const uint2& b) {
    asm("mma.sync.aligned.m16n8k8.row.col.f32.tf32.tf32.f32 "
        "{%0,%1,%2,%3}, {%4,%5,%6,%7}, {%8,%9}, {%0,%1,%2,%3};"
        : "+f"(c[0]), "+f"(c[1]), "+f"(c[2]), "+f"(c[3])
        : "r"(a.x), "r"(a.y), "r"(a.z), "r"(a.w), "r"(b.x), "r"(b.y));
}

// -------- zero counters --------
__global__ void zero_kernel() {
    int i = blockIdx.x * blockDim.x + threadIdx.x;
    if (i < MAXN) d_cnt[i] = 0;
    if (i < F) d_gsum[i] = 0.f;
}

// -------- bucket fill: csr[row][p++] = col --------
__global__ void fill_kernel(const int* __restrict__ ei, int E) {
    int e = blockIdx.x * blockDim.x + threadIdx.x;
    if (e < E) {
        int r = ei[e];
        int p = atomicAdd(&d_cnt[r], 1);
        if (p < CAP) d_csr[((size_t)r << 6) + p] = ei[E + e];
    }
}

// -------- per-position norm: s[i] = dis[row[i]] * dis[col[i]] --------
__global__ void s_kernel(const int* __restrict__ ei, int n, int E) {
    int i = blockIdx.x * blockDim.x + threadIdx.x;
    if (i < n) {
        float dr = (float)d_cnt[ei[i]];
        float dc = (float)d_cnt[ei[E + i]];
        float a = dr > 0.f ? rsqrtf(dr) : 0.f;
        float b = dc > 0.f ? rsqrtf(dc) : 0.f;
        d_s[i] = a * b;
    }
}

// -------- one-time W -> fragment-layout transform (grid 8 x 512) --------
//   idx = ((nc*16+ks)*32+lp)*2 + sb;  H at dst[idx], L at dst[16384+idx]
__global__ void wprep_kernel(const float* __restrict__ W, uint32_t* __restrict__ dst) {
    int lin = blockIdx.x * 512 + threadIdx.x;   // 0..4095
    int k = lin >> 5, q = lin & 31;
    float4 wv4 = *(const float4*)(W + k * F + q * 4);
    int ks = k >> 3, kk = k & 7;
    int btig = kk & 3, sb = kk >> 2;
    int sw = ks & 7;
    float wv[4] = { wv4.x, wv4.y, wv4.z, wv4.w };
    #pragma unroll
    for (int j = 0; j < 4; j++) {
        int c = q * 4 + j;
        int nc = c >> 3, cg = c & 7;
        int lp = (cg * 4 + btig) ^ sw;
        int idx = ((nc * 16 + ks) * 32 + lp) * 2 + sb;
        uint32_t wh = f2tf32(wv[j]);
        float rem = wv[j] - __uint_as_float(wh);
        dst[idx] = wh;
        dst[16384 + idx] = f2tf32(rem);
    }
}

// -------- fused tensor-core GEMM: out[i] = (relu?(X[i]) @ W + b) * s[i] --------
// Block 128x128, K=128, 256 threads (8 warps, 2x4 warp grid, warp tile 64x32).
// A fragments staged in smem (64KB). B fragments (Wh+Wl, precomputed by
// wprep) are read DIRECTLY from global in the mainloop — the 128KB region is
// L2/L1-resident and each warp-load covers a contiguous 256B line pair.
// smem 64KB + ~115 regs -> 2 blocks/SM: staging/epilogue of one block
// overlaps the other's mainloop (was 1 block/SM, serial phases).
// Fragment maps (PTX m16n8k8.tf32): g=lane>>2, tig=lane&3;
//   A: a0=A[g][tig] a1=A[g+8][tig] a2=A[g][tig+4] a3=A[g+8][tig+4]
//   B: b0=B[tig][col_g] b1=B[tig+4][col_g]
//   D: c0=D[g][2tig] c1=D[g][2tig+1] c2=D[g+8][2tig] c3=D[g+8][2tig+1]
#define GSM_BYTES 65536   // A fragments only: 8 mc x 16 ks x 32 lanes x 4 u32

__global__ __launch_bounds__(256, 2)
void gemm_kernel(const float* __restrict__ X, const uint32_t* __restrict__ wf,
                 const float* __restrict__ bias,
                 float* __restrict__ out, int n, int relu_in) {
    extern __shared__ float smf[];
    uint32_t* smu = (uint32_t*)smf;
    const int tid = threadIdx.x;
    const int w = tid >> 5, l = tid & 31;
    const int wm = w >> 2, wn = w & 3;
    const int g = l >> 2, tig = l & 3;
    const int rbase = blockIdx.x * 128;

    // ---- stage A fragments: 4096 float4, 16 per thread
    #pragma unroll
    for (int it = 0; it < 16; it++) {
        int lin = it * 256 + tid;
        int r = lin >> 5, q = lin & 31;
        int row = rbase + r;
        float4 v = make_float4(0.f, 0.f, 0.f, 0.f);
        if (row < n) v = ((const float4*)(X + (size_t)row * F))[q];
        if (relu_in) {
            v.x = fmaxf(v.x, 0.f); v.y = fmaxf(v.y, 0.f);
            v.z = fmaxf(v.z, 0.f); v.w = fmaxf(v.w, 0.f);
        }
        int mc = r >> 4, gp = r & 15, gg = gp & 7;
        int ks = q >> 1;
        int slot = ((q & 1) << 1) + (gp >> 3);     // {a0,a1,a2,a3} position
        int base16 = (mc * 16 + ks) * 32;
        int sw = ks & 7;
        float vv[4] = { v.x, v.y, v.z, v.w };
        #pragma unroll
        for (int j = 0; j < 4; j++) {
            int lp = (gg * 4 + j) ^ sw;            // j = tig of element k0+j
            smu[(base16 + lp) * 4 + slot] = f2tf32(vv[j]);
        }
    }
    __syncthreads();

    // ---- mainloop: warp tile 64x32 = 4 m-tiles x 4 n-tiles
    float acc[4][4][4];
    #pragma unroll
    for (int mt = 0; mt < 4; mt++)
        #pragma unroll
        for (int nt = 0; nt < 4; nt++)
            #pragma unroll
            for (int j = 0; j < 4; j++) acc[mt][nt][j] = 0.f;

    #pragma unroll 4
    for (int ks = 0; ks < 16; ks++) {
        int lp = l ^ (ks & 7);
        uint4 af[4];
        #pragma unroll
        for (int mt = 0; mt < 4; mt++)
            af[mt] = *(const uint4*)&smu[(((wm * 4 + mt) * 16 + ks) * 32 + lp) * 4];
        uint2 bh[4], bl[4];
        #pragma unroll
        for (int nt = 0; nt < 4; nt++) {
            int bidx = (((wn * 4 + nt) * 16 + ks) * 32 + lp) * 2;
            bh[nt] = *(const uint2*)&wf[bidx];
            bl[nt] = *(const uint2*)&wf[16384 + bidx];
        }
        #pragma unroll
        for (int mt = 0; mt < 4; mt++)
            #pragma unroll
            for (int nt = 0; nt < 4; nt++) {
                mma_tf32(acc[mt][nt], af[mt], bh[nt]);
                mma_tf32(acc[mt][nt], af[mt], bl[nt]);
            }
    }

    // ---- epilogue: bias + degree-norm scale, write fp32
    #pragma unroll
    for (int mt = 0; mt < 4; mt++) {
        int row_lo = rbase + wm * 64 + mt * 16 + g;
        int row_hi = row_lo + 8;
        float s_lo = (row_lo < n) ? d_s[row_lo] : 0.f;
        float s_hi = (row_hi < n) ? d_s[row_hi] : 0.f;
        #pragma unroll
        for (int nt = 0; nt < 4; nt++) {
            int col = wn * 32 + nt * 8 + tig * 2;
            float b0 = bias[col], b1 = bias[col + 1];
            if (row_lo < n) {
                float2 o = make_float2((acc[mt][nt][0] + b0) * s_lo,
                                       (acc[mt][nt][1] + b1) * s_lo);
                *(float2*)(out + (size_t)row_lo * F + col) = o;
            }
            if (row_hi < n) {
                float2 o = make_float2((acc[mt][nt][2] + b0) * s_hi,
                                       (acc[mt][nt][3] + b1) * s_hi);
                *(float2*)(out + (size_t)row_hi * F + col) = o;
            }
        }
    }
}

// -------- gather: dst[r] = sum over bucket(r) of src[col]  (warp per row) --------
__global__ void gather_kernel(const float* __restrict__ src,
                              float* __restrict__ dst, int n) {
    int warp = (blockIdx.x * blockDim.x + threadIdx.x) >> 5;
    int lane = threadIdx.x & 31;
    int nw = (gridDim.x * blockDim.x) >> 5;
    for (int r = warp; r < n; r += nw) {
        int cnt = d_cnt[r]; if (cnt > CAP) cnt = CAP;
        float4 acc = make_float4(0.f, 0.f, 0.f, 0.f);
        size_t base = (size_t)r << 6;
        for (int i = 0; i < cnt; i++) {
            int c = d_csr[base + i];
            float4 v = ((const float4*)(src + (size_t)c * F))[lane];
            acc.x += v.x; acc.y += v.y; acc.z += v.z; acc.w += v.w;
        }
        ((float4*)(dst + (size_t)r * F))[lane] = acc;
    }
}

// -------- gather + relu + column-sum fusion (never materializes agg2) --------
__global__ void gather_mean_kernel(const float* __restrict__ src, int n) {
    __shared__ float smr[128];
    int t = threadIdx.x;
    if (t < 128) smr[t] = 0.f;
    __syncthreads();
    int warp = (blockIdx.x * blockDim.x + t) >> 5;
    int lane = t & 31;
    int nw = (gridDim.x * blockDim.x) >> 5;
    float4 ps = make_float4(0.f, 0.f, 0.f, 0.f);
    for (int r = warp; r < n; r += nw) {
        int cnt = d_cnt[r]; if (cnt > CAP) cnt = CAP;
        float4 acc = make_float4(0.f, 0.f, 0.f, 0.f);
        size_t base = (size_t)r << 6;
        for (int i = 0; i < cnt; i++) {
            int c = d_csr[base + i];
            float4 v = ((const float4*)(src + (size_t)c * F))[lane];
            acc.x += v.x; acc.y += v.y; acc.z += v.z; acc.w += v.w;
        }
        ps.x += fmaxf(acc.x, 0.f); ps.y += fmaxf(acc.y, 0.f);
        ps.z += fmaxf(acc.z, 0.f); ps.w += fmaxf(acc.w, 0.f);
    }
    atomicAdd(&smr[lane * 4 + 0], ps.x);
    atomicAdd(&smr[lane * 4 + 1], ps.y);
    atomicAdd(&smr[lane * 4 + 2], ps.z);
    atomicAdd(&smr[lane * 4 + 3], ps.w);
    __syncthreads();
    if (t < 128) atomicAdd(&d_gsum[t], smr[t]);
}

// -------- latent head (1 block, 128 threads) --------
__global__ void head_kernel(const float* __restrict__ eps,
                            const float* __restrict__ Wmu, const float* __restrict__ bmu,
                            const float* __restrict__ Wlv, const float* __restrict__ blv,
                            const float* __restrict__ Wn,  const float* __restrict__ bn,
                            const float* __restrict__ We1, const float* __restrict__ be1,
                            const float* __restrict__ We2, const float* __restrict__ be2,
                            float* __restrict__ out, int n, int E) {
    __shared__ float zs[32];
    __shared__ float ehs[128];
    int t = threadIdx.x;
    float invN = 1.0f / (float)n;
    size_t ofs = 16 + (size_t)E * 4;
    if (t < 32) {
        float mu = bmu[t], lv = blv[t];
        for (int c = 0; c < 128; c++) {
            float g = d_gsum[c] * invN;
            mu += g * Wmu[c * 32 + t];
            lv += g * Wlv[c * 32 + t];
        }
        zs[t] = mu + eps[t] * expf(0.5f * lv);
        out[ofs + t] = mu;
        out[ofs + 32 + t] = lv;
    }
    __syncthreads();
    if (t < 16) {
        float v = bn[t];
        for (int j = 0; j < 32; j++) v += zs[j] * Wn[j * 16 + t];
        out[t] = v;
    }
    {
        float v = be1[t];
        for (int k = 0; k < 64; k++) v += zs[k & 31] * We1[k * 128 + t];
        ehs[t] = fmaxf(v, 0.f);
    }
    __syncthreads();
    if (t < 4) {
        float v = be2[t];
        for (int h2 = 0; h2 < 128; h2++) v += ehs[h2] * We2[h2 * 4 + t];
        d_el[t] = v;
    }
}

// -------- broadcast identical edge logits --------
__global__ void bcast_kernel(float* __restrict__ out, int E) {
    int e = blockIdx.x * blockDim.x + threadIdx.x;
    float4 v = *(const float4*)d_el;
    if (e < E) ((float4*)(out + 16))[e] = v;
}

extern "C" void kernel_launch(void* const* d_in, const int* in_sizes, int n_in,
                              void* d_out, int out_size) {
    const float* x   = (const float*)d_in[0];
    const int*   ei  = (const int*)d_in[1];      // int32 (JAX x64 disabled)
    const float* eps = (const float*)d_in[2];
    const float* W1  = (const float*)d_in[3];
    const float* b1  = (const float*)d_in[4];
    const float* W2  = (const float*)d_in[5];
    const float* b2  = (const float*)d_in[6];
    const float* Wmu = (const float*)d_in[7];
    const float* bmu = (const float*)d_in[8];
    const float* Wlv = (const float*)d_in[9];
    const float* blv = (const float*)d_in[10];
    const float* Wn  = (const float*)d_in[11];
    const float* bn  = (const float*)d_in[12];
    const float* We1 = (const float*)d_in[13];
    const float* be1 = (const float*)d_in[14];
    const float* We2 = (const float*)d_in[15];
    const float* be2 = (const float*)d_in[16];
    float* out = (float*)d_out;

    int n = in_sizes[0] / F;       // 500000
    int E = in_sizes[1] / 2;       // 500000

    float* bufA_p = nullptr;
    float* bufB_p = nullptr;
    uint32_t* wf1_p = nullptr;
    uint32_t* wf2_p = nullptr;
    cudaGetSymbolAddress((void**)&bufA_p, d_bufA);
    cudaGetSymbolAddress((void**)&bufB_p, d_bufB);
    cudaGetSymbolAddress((void**)&wf1_p, d_wf1);
    cudaGetSymbolAddress((void**)&wf2_p, d_wf2);

    cudaFuncSetAttribute(gemm_kernel,
                         cudaFuncAttributeMaxDynamicSharedMemorySize, GSM_BYTES);

    int gblocks = (n + 127) / 128;

    zero_kernel<<<(MAXN + 255) / 256, 256>>>();
    fill_kernel<<<(E + 255) / 256, 256>>>(ei, E);
    s_kernel<<<(n + 255) / 256, 256>>>(ei, n, E);
    wprep_kernel<<<8, 512>>>(W1, wf1_p);
    wprep_kernel<<<8, 512>>>(W2, wf2_p);

    // conv1: bufA = (x@W1+b1)*s ; bufB = gather(bufA)
    gemm_kernel<<<gblocks, 256, GSM_BYTES>>>(x, wf1_p, b1, bufA_p, n, 0);
    gather_kernel<<<2048, 256>>>(bufA_p, bufB_p, n);

    // conv2: bufA = (relu(bufB)@W2+b2)*s ; fused gather+relu+colsum
    gemm_kernel<<<gblocks, 256, GSM_BYTES>>>(bufB_p, wf2_p, b2, bufA_p, n, 1);
    gather_mean_kernel<<<2048, 256>>>(bufA_p, n);

    // latent head ; edge-logit broadcast
    head_kernel<<<1, 128>>>(eps, Wmu, bmu, Wlv, blv, Wn, bn, We1, be1, We2, be2,
                            out, n, E);
    bcast_kernel<<<(E + 255) / 256, 256>>>(out, E);
}